// round 6
// baseline (speedup 1.0000x reference)
#include <cuda_runtime.h>
#include <cuda_bf16.h>
#include <cstdint>
#include <stdint.h>
#include <math.h>

// Problem constants
#define Dd 1024   // feature dim
#define Cc 1000   // prototypes
#define Bb 128    // batch
#define RT 1128   // Cc + Bb stacked rows
#define MP 1152   // RT padded to multiple of 64
#define KS 8      // split-K for cross-dot gemm
#define KC (Dd / KS)

// Scratch (device globals — no allocation allowed)
__device__ __nv_bfloat16 g_Abf[MP * Dd];   // [mu; x; 0] bf16          2.25 MB
__device__ __nv_bfloat16 g_Bbf[Dd * Dd];   // tril(L)^T bf16 [n][k]    2 MB
__device__ __nv_bfloat16 g_MAbf[MP * Dd];  // MA = [mu;x] @ tril(L)    2.25 MB
__device__ float g_qeps[RT];               // 1e-6 * ||In_r||^2
__device__ float g_q[RT];                  // ||MA_r||^2 + qeps
__device__ float g_bd[RT];                 // beta . In_r
__device__ float g_part[KS * Bb * Dd];     // split-K partial cross dots

// ---------------------------------------------------------------------------
// mma / ldmatrix helpers
// ---------------------------------------------------------------------------
__device__ __forceinline__ void ldsm_x4(uint32_t& r0, uint32_t& r1,
                                        uint32_t& r2, uint32_t& r3,
                                        uint32_t addr) {
    asm volatile("ldmatrix.sync.aligned.m8n8.x4.shared.b16 {%0,%1,%2,%3}, [%4];\n"
                 : "=r"(r0), "=r"(r1), "=r"(r2), "=r"(r3) : "r"(addr));
}

__device__ __forceinline__ void mma_bf16(float* d, const uint32_t* a,
                                         uint32_t b0, uint32_t b1) {
    asm volatile(
        "mma.sync.aligned.m16n8k16.row.col.f32.bf16.bf16.f32 "
        "{%0,%1,%2,%3}, {%4,%5,%6,%7}, {%8,%9}, {%0,%1,%2,%3};\n"
        : "+f"(d[0]), "+f"(d[1]), "+f"(d[2]), "+f"(d[3])
        : "r"(a[0]), "r"(a[1]), "r"(a[2]), "r"(a[3]), "r"(b0), "r"(b1));
}

// ---------------------------------------------------------------------------
// 0a) prepA: g_Abf = bf16([mu; x; zeros]) FUSED with input row stats:
//     g_qeps[r] = 1e-6*||in_r||^2 ; g_bd[r] = beta . in_r
//     One block per row (256 thr x 4 elems = 1024 = Dd).
// ---------------------------------------------------------------------------
__global__ __launch_bounds__(256) void prepA(const float* __restrict__ x,
                                             const float* __restrict__ mu,
                                             const float* __restrict__ beta) {
    int r = blockIdx.x;
    int tid = threadIdx.x;
    int k = tid * 4;
    float4 v = make_float4(0.f, 0.f, 0.f, 0.f);
    if (r < Cc)      v = *reinterpret_cast<const float4*>(mu + (size_t)r * Dd + k);
    else if (r < RT) v = *reinterpret_cast<const float4*>(x + (size_t)(r - Cc) * Dd + k);
    __nv_bfloat162 p0 = __floats2bfloat162_rn(v.x, v.y);
    __nv_bfloat162 p1 = __floats2bfloat162_rn(v.z, v.w);
    uint2 o;
    o.x = *reinterpret_cast<uint32_t*>(&p0);
    o.y = *reinterpret_cast<uint32_t*>(&p1);
    *reinterpret_cast<uint2*>(g_Abf + (size_t)r * Dd + k) = o;

    if (r >= RT) return;  // pad rows: no stats

    float4 b4 = *reinterpret_cast<const float4*>(beta + k);
    float sin_ = v.x * v.x + v.y * v.y + v.z * v.z + v.w * v.w;
    float sb = b4.x * v.x + b4.y * v.y + b4.z * v.z + b4.w * v.w;

#pragma unroll
    for (int off = 16; off > 0; off >>= 1) {
        sin_ += __shfl_xor_sync(0xFFFFFFFFu, sin_, off);
        sb += __shfl_xor_sync(0xFFFFFFFFu, sb, off);
    }
    __shared__ float red[2][8];
    int wid = tid >> 5, lane = tid & 31;
    if (lane == 0) { red[0][wid] = sin_; red[1][wid] = sb; }
    __syncthreads();
    if (tid == 0) {
        float t0 = 0.f, t1 = 0.f;
#pragma unroll
        for (int wq = 0; wq < 8; wq++) { t0 += red[0][wq]; t1 += red[1][wq]; }
        g_qeps[r] = 1e-6f * t0;
        g_bd[r] = t1;
    }
}

// ---------------------------------------------------------------------------
// 0b) prepL: g_Bbf[n][k] = bf16( k>=n ? L[k][n] : 0 )   (tril + transpose)
// ---------------------------------------------------------------------------
__global__ void prepL(const float* __restrict__ L) {
    __shared__ float t[32][33];
    int bx = blockIdx.x * 32;  // k base
    int by = blockIdx.y * 32;  // n base
    int tx = threadIdx.x, ty = threadIdx.y;  // block (32, 8)
#pragma unroll
    for (int i = ty; i < 32; i += 8)
        t[i][tx] = L[(size_t)(bx + i) * Dd + by + tx];
    __syncthreads();
#pragma unroll
    for (int i = ty; i < 32; i += 8) {
        int n = by + i, k = bx + tx;
        float v = (k >= n) ? t[tx][i] : 0.f;
        g_Bbf[(size_t)n * Dd + k] = __float2bfloat16(v);
    }
}

// ---------------------------------------------------------------------------
// 1) gemm_ma_mma: g_MAbf[m][n] = sum_k g_Abf[m][k] * g_Bbf[n][k]  (NT, bf16 HMMA)
//    BM=BN=64, BK=32, 128 thr, 2x2 warps, warp tile 32x32. Triangular K-skip.
// ---------------------------------------------------------------------------
__global__ __launch_bounds__(128) void gemm_ma_mma() {
    __shared__ __align__(16) __nv_bfloat16 As[64][40];
    __shared__ __align__(16) __nv_bfloat16 Bs[64][40];
    int bm = blockIdx.x * 64;
    int bn = blockIdx.y * 64;
    int tid = threadIdx.x;
    int lane = tid & 31, w = tid >> 5;
    int wm = (w & 1) * 32, wn = (w >> 1) * 32;

    int lr = tid >> 1;             // 0..63 (tile row)
    int lk = (tid & 1) * 16;       // 0 / 16 (bf16 units)
    const __nv_bfloat16* aptr = g_Abf + (size_t)(bm + lr) * Dd + lk;
    const __nv_bfloat16* bptr = g_Bbf + (size_t)(bn + lr) * Dd + lk;

    float acc[2][4][4];
#pragma unroll
    for (int mt = 0; mt < 2; mt++)
#pragma unroll
        for (int nt = 0; nt < 4; nt++)
#pragma unroll
            for (int e = 0; e < 4; e++) acc[mt][nt][e] = 0.f;

    uint32_t aAddr[2], bAddr[2];
#pragma unroll
    for (int t = 0; t < 2; t++) {
        aAddr[t] = (uint32_t)__cvta_generic_to_shared(
            &As[wm + t * 16 + (lane & 15)][(lane >> 4) * 8]);
        bAddr[t] = (uint32_t)__cvta_generic_to_shared(
            &Bs[wn + t * 16 + (lane & 15)][(lane >> 4) * 8]);
    }

    int kstart = bn;  // tril skip: L^T[n][k] = 0 for k < n
    uint4 pa0 = *reinterpret_cast<const uint4*>(aptr + kstart);
    uint4 pa1 = *reinterpret_cast<const uint4*>(aptr + kstart + 8);
    uint4 pb0 = *reinterpret_cast<const uint4*>(bptr + kstart);
    uint4 pb1 = *reinterpret_cast<const uint4*>(bptr + kstart + 8);

    for (int k0 = kstart; k0 < Dd; k0 += 32) {
        *reinterpret_cast<uint4*>(&As[lr][lk]) = pa0;
        *reinterpret_cast<uint4*>(&As[lr][lk + 8]) = pa1;
        *reinterpret_cast<uint4*>(&Bs[lr][lk]) = pb0;
        *reinterpret_cast<uint4*>(&Bs[lr][lk + 8]) = pb1;
        __syncthreads();
        if (k0 + 32 < Dd) {
            pa0 = *reinterpret_cast<const uint4*>(aptr + k0 + 32);
            pa1 = *reinterpret_cast<const uint4*>(aptr + k0 + 40);
            pb0 = *reinterpret_cast<const uint4*>(bptr + k0 + 32);
            pb1 = *reinterpret_cast<const uint4*>(bptr + k0 + 40);
        }
#pragma unroll
        for (int ks = 0; ks < 2; ks++) {
            uint32_t off = (uint32_t)(ks * 32);  // bytes (16 bf16)
            uint32_t a0[4], a1[4], br0[4], br1[4];
            ldsm_x4(a0[0], a0[1], a0[2], a0[3], aAddr[0] + off);
            ldsm_x4(a1[0], a1[1], a1[2], a1[3], aAddr[1] + off);
            ldsm_x4(br0[0], br0[1], br0[2], br0[3], bAddr[0] + off);
            ldsm_x4(br1[0], br1[1], br1[2], br1[3], bAddr[1] + off);
#pragma unroll
            for (int mt = 0; mt < 2; mt++) {
                uint32_t* a = mt ? a1 : a0;
                mma_bf16(acc[mt][0], a, br0[0], br0[2]);
                mma_bf16(acc[mt][1], a, br0[1], br0[3]);
                mma_bf16(acc[mt][2], a, br1[0], br1[2]);
                mma_bf16(acc[mt][3], a, br1[1], br1[3]);
            }
        }
        __syncthreads();
    }

    int mrow = lane >> 2;
    int ncol = (lane & 3) * 2;
#pragma unroll
    for (int mt = 0; mt < 2; mt++)
#pragma unroll
        for (int nt = 0; nt < 4; nt++) {
            int row = bm + wm + mt * 16 + mrow;
            int col = bn + wn + nt * 8 + ncol;
            __nv_bfloat162 lo = __floats2bfloat162_rn(acc[mt][nt][0], acc[mt][nt][1]);
            __nv_bfloat162 hi = __floats2bfloat162_rn(acc[mt][nt][2], acc[mt][nt][3]);
            *reinterpret_cast<__nv_bfloat162*>(g_MAbf + (size_t)row * Dd + col) = lo;
            *reinterpret_cast<__nv_bfloat162*>(g_MAbf + (size_t)(row + 8) * Dd + col) = hi;
        }
}

// ---------------------------------------------------------------------------
// 2) manorm: g_q[r] = ||MAbf_r||^2 + g_qeps[r]   (reads only MAbf: 2KB/row)
//    128 threads x 8 bf16 (one uint4) = 1024 elems.
// ---------------------------------------------------------------------------
__global__ __launch_bounds__(128) void manorm() {
    int r = blockIdx.x;
    int tid = threadIdx.x;
    const __nv_bfloat16* ma = g_MAbf + (size_t)r * Dd + tid * 8;
    uint4 u = *reinterpret_cast<const uint4*>(ma);
    float s = 0.f;
    uint32_t uw[4] = {u.x, u.y, u.z, u.w};
#pragma unroll
    for (int i = 0; i < 4; i++) {
        __nv_bfloat162 p = *reinterpret_cast<__nv_bfloat162*>(&uw[i]);
        float f0 = __bfloat162float(p.x), f1 = __bfloat162float(p.y);
        s += f0 * f0 + f1 * f1;
    }
#pragma unroll
    for (int off = 16; off > 0; off >>= 1)
        s += __shfl_xor_sync(0xFFFFFFFFu, s, off);
    __shared__ float red[4];
    int wid = tid >> 5, lane = tid & 31;
    if (lane == 0) red[wid] = s;
    __syncthreads();
    if (tid == 0)
        g_q[r] = red[0] + red[1] + red[2] + red[3] + g_qeps[r];
}

// ---------------------------------------------------------------------------
// 3) dot_mma: part[z][b][c] = sum_{k in chunk z} MAbf[Cc+b][k] * MAbf[c][k]
//    Same NT HMMA structure, split-K=8.
// ---------------------------------------------------------------------------
__global__ __launch_bounds__(128) void dot_mma() {
    __shared__ __align__(16) __nv_bfloat16 As[64][40];
    __shared__ __align__(16) __nv_bfloat16 Bs[64][40];
    int bm = blockIdx.x * 64;                // b offset
    int bn = blockIdx.y * 64;                // c offset
    int kb = blockIdx.z * KC;                // k chunk base
    int tid = threadIdx.x;
    int lane = tid & 31, w = tid >> 5;
    int wm = (w & 1) * 32, wn = (w >> 1) * 32;

    int lr = tid >> 1;
    int lk = (tid & 1) * 16;
    const __nv_bfloat16* aptr = g_MAbf + (size_t)(Cc + bm + lr) * Dd + kb + lk;
    const __nv_bfloat16* bptr = g_MAbf + (size_t)(bn + lr) * Dd + kb + lk;

    float acc[2][4][4];
#pragma unroll
    for (int mt = 0; mt < 2; mt++)
#pragma unroll
        for (int nt = 0; nt < 4; nt++)
#pragma unroll
            for (int e = 0; e < 4; e++) acc[mt][nt][e] = 0.f;

    uint32_t aAddr[2], bAddr[2];
#pragma unroll
    for (int t = 0; t < 2; t++) {
        aAddr[t] = (uint32_t)__cvta_generic_to_shared(
            &As[wm + t * 16 + (lane & 15)][(lane >> 4) * 8]);
        bAddr[t] = (uint32_t)__cvta_generic_to_shared(
            &Bs[wn + t * 16 + (lane & 15)][(lane >> 4) * 8]);
    }

    uint4 qa0 = *reinterpret_cast<const uint4*>(aptr);
    uint4 qa1 = *reinterpret_cast<const uint4*>(aptr + 8);
    uint4 qb0 = *reinterpret_cast<const uint4*>(bptr);
    uint4 qb1 = *reinterpret_cast<const uint4*>(bptr + 8);

#pragma unroll 1
    for (int k0 = 0; k0 < KC; k0 += 32) {
        *reinterpret_cast<uint4*>(&As[lr][lk]) = qa0;
        *reinterpret_cast<uint4*>(&As[lr][lk + 8]) = qa1;
        *reinterpret_cast<uint4*>(&Bs[lr][lk]) = qb0;
        *reinterpret_cast<uint4*>(&Bs[lr][lk + 8]) = qb1;
        __syncthreads();
        if (k0 + 32 < KC) {
            qa0 = *reinterpret_cast<const uint4*>(aptr + k0 + 32);
            qa1 = *reinterpret_cast<const uint4*>(aptr + k0 + 40);
            qb0 = *reinterpret_cast<const uint4*>(bptr + k0 + 32);
            qb1 = *reinterpret_cast<const uint4*>(bptr + k0 + 40);
        }
#pragma unroll
        for (int ks = 0; ks < 2; ks++) {
            uint32_t off = (uint32_t)(ks * 32);
            uint32_t a0[4], a1[4], br0[4], br1[4];
            ldsm_x4(a0[0], a0[1], a0[2], a0[3], aAddr[0] + off);
            ldsm_x4(a1[0], a1[1], a1[2], a1[3], aAddr[1] + off);
            ldsm_x4(br0[0], br0[1], br0[2], br0[3], bAddr[0] + off);
            ldsm_x4(br1[0], br1[1], br1[2], br1[3], bAddr[1] + off);
#pragma unroll
            for (int mt = 0; mt < 2; mt++) {
                uint32_t* a = mt ? a1 : a0;
                mma_bf16(acc[mt][0], a, br0[0], br0[2]);
                mma_bf16(acc[mt][1], a, br0[1], br0[3]);
                mma_bf16(acc[mt][2], a, br1[0], br1[2]);
                mma_bf16(acc[mt][3], a, br1[1], br1[3]);
            }
        }
        __syncthreads();
    }

    int mrow = lane >> 2;
    int ncol = (lane & 3) * 2;
    float* outz = g_part + (size_t)blockIdx.z * Bb * Dd;
#pragma unroll
    for (int mt = 0; mt < 2; mt++)
#pragma unroll
        for (int nt = 0; nt < 4; nt++) {
            int row = bm + wm + mt * 16 + mrow;
            int col = bn + wn + nt * 8 + ncol;
            float2 lo = make_float2(acc[mt][nt][0], acc[mt][nt][1]);
            float2 hi = make_float2(acc[mt][nt][2], acc[mt][nt][3]);
            *reinterpret_cast<float2*>(outz + (size_t)row * Dd + col) = lo;
            *reinterpret_cast<float2*>(outz + (size_t)(row + 8) * Dd + col) = hi;
        }
}

// ---------------------------------------------------------------------------
// 4) Finalize (vectorized: 4 c's per thread via float4)
// ---------------------------------------------------------------------------
#define C4 (Cc / 4)   // 250
__global__ __launch_bounds__(128) void finalize(const float* __restrict__ lmbda,
                                                const float* __restrict__ scale,
                                                float* __restrict__ out) {
    int idx = blockIdx.x * 128 + threadIdx.x;
    if (idx >= Bb * C4) return;
    int b = idx / C4;
    int c = (idx - b * C4) * 4;

    float4 s = make_float4(0.f, 0.f, 0.f, 0.f);
#pragma unroll
    for (int ks = 0; ks < KS; ks++) {
        float4 p = *reinterpret_cast<const float4*>(
            g_part + ((size_t)ks * Bb + b) * Dd + c);
        s.x += p.x; s.y += p.y; s.z += p.z; s.w += p.w;
    }
    float qb = g_q[Cc + b];
    float bdb = g_bd[Cc + b];
    float lm = *lmbda;
    float sc = *scale;
    float4 o;
    {
        float quad = qb + g_q[c + 0] - 2.f * s.x;
        float bd = bdb - g_bd[c + 0];
        o.x = -sc * (sqrtf(quad + 1e-6f) + lm * sqrtf(bd * bd + 1e-6f));
    }
    {
        float quad = qb + g_q[c + 1] - 2.f * s.y;
        float bd = bdb - g_bd[c + 1];
        o.y = -sc * (sqrtf(quad + 1e-6f) + lm * sqrtf(bd * bd + 1e-6f));
    }
    {
        float quad = qb + g_q[c + 2] - 2.f * s.z;
        float bd = bdb - g_bd[c + 2];
        o.z = -sc * (sqrtf(quad + 1e-6f) + lm * sqrtf(bd * bd + 1e-6f));
    }
    {
        float quad = qb + g_q[c + 3] - 2.f * s.w;
        float bd = bdb - g_bd[c + 3];
        o.w = -sc * (sqrtf(quad + 1e-6f) + lm * sqrtf(bd * bd + 1e-6f));
    }
    *reinterpret_cast<float4*>(out + (size_t)b * Cc + c) = o;
}

// ---------------------------------------------------------------------------
extern "C" void kernel_launch(void* const* d_in, const int* in_sizes, int n_in,
                              void* d_out, int out_size) {
    const float *x = nullptr, *mu = nullptr, *beta = nullptr, *L = nullptr;
    const float *lmbda = nullptr, *scale = nullptr;
    for (int i = 0; i < n_in; i++) {
        const float* p = (const float*)d_in[i];
        switch (in_sizes[i]) {
            case Bb * Dd:  x = p; break;
            case Cc * Dd:  mu = p; break;
            case Dd:       beta = p; break;
            case Dd * Dd:  L = p; break;
            case 1:        if (!lmbda) lmbda = p; else scale = p; break;
            default: break;
        }
    }

    prepA<<<MP, 256>>>(x, mu, beta);
    prepL<<<dim3(Dd / 32, Dd / 32), dim3(32, 8)>>>(L);
    gemm_ma_mma<<<dim3(MP / 64, Dd / 64), 128>>>();
    manorm<<<RT, 128>>>();
    dot_mma<<<dim3(Bb / 64, Dd / 64, KS), 128>>>();
    finalize<<<(Bb * C4 + 127) / 128, 128>>>(lmbda, scale, (float*)d_out);
}

// round 7
// speedup vs baseline: 1.1312x; 1.1312x over previous
#include <cuda_runtime.h>
#include <cuda_bf16.h>
#include <cstdint>
#include <stdint.h>
#include <math.h>

// Problem constants
#define Dd 1024   // feature dim
#define Cc 1000   // prototypes
#define Bb 128    // batch
#define RT 1128   // Cc + Bb stacked rows
#define MP 1152   // RT padded to multiple of 64
#define KS 8      // split-K for cross-dot gemm
#define KC (Dd / KS)

// Scratch (device globals — no allocation allowed)
__device__ __nv_bfloat16 g_Abf[MP * Dd];   // [mu; x; 0] bf16          2.25 MB
__device__ __nv_bfloat16 g_Bbf[Dd * Dd];   // tril(L)^T bf16 [n][k]    2 MB
__device__ __nv_bfloat16 g_MAbf[MP * Dd];  // MA = [mu;x] @ tril(L)    2.25 MB
__device__ float g_q[MP];                  // ||MA_r||^2 + 1e-6||in_r||^2 (atomic)
__device__ float g_bd[RT];                 // beta . in_r
__device__ float g_dots[Bb * Dd];          // cross dots A_b.M_c (atomic, c padded)

// ---------------------------------------------------------------------------
// mma / ldmatrix helpers
// ---------------------------------------------------------------------------
__device__ __forceinline__ void ldsm_x4(uint32_t& r0, uint32_t& r1,
                                        uint32_t& r2, uint32_t& r3,
                                        uint32_t addr) {
    asm volatile("ldmatrix.sync.aligned.m8n8.x4.shared.b16 {%0,%1,%2,%3}, [%4];\n"
                 : "=r"(r0), "=r"(r1), "=r"(r2), "=r"(r3) : "r"(addr));
}

__device__ __forceinline__ void mma_bf16(float* d, const uint32_t* a,
                                         uint32_t b0, uint32_t b1) {
    asm volatile(
        "mma.sync.aligned.m16n8k16.row.col.f32.bf16.bf16.f32 "
        "{%0,%1,%2,%3}, {%4,%5,%6,%7}, {%8,%9}, {%0,%1,%2,%3};\n"
        : "+f"(d[0]), "+f"(d[1]), "+f"(d[2]), "+f"(d[3])
        : "r"(a[0]), "r"(a[1]), "r"(a[2]), "r"(a[3]), "r"(b0), "r"(b1));
}

// ---------------------------------------------------------------------------
// 0) prep (single launch, block-range dispatch):
//    blocks [0, MP):          bf16 convert row r of [mu; x; 0] + input stats
//                             (seeds g_q[r] = 1e-6*||in||^2, writes g_bd)
//    blocks [MP, MP+1024):    tril+transpose 32x32 tile of L -> g_Bbf
//    blocks [MP+1024, +128):  zero g_dots
// ---------------------------------------------------------------------------
#define PREP_L0 MP
#define PREP_Z0 (MP + 1024)
__global__ __launch_bounds__(256) void prep(const float* __restrict__ x,
                                            const float* __restrict__ mu,
                                            const float* __restrict__ beta,
                                            const float* __restrict__ L) {
    int bid = blockIdx.x;
    int tid = threadIdx.x;

    if (bid < PREP_L0) {
        // ---- prepA: one row ----
        int r = bid;
        int k = tid * 4;
        float4 v = make_float4(0.f, 0.f, 0.f, 0.f);
        if (r < Cc)      v = *reinterpret_cast<const float4*>(mu + (size_t)r * Dd + k);
        else if (r < RT) v = *reinterpret_cast<const float4*>(x + (size_t)(r - Cc) * Dd + k);
        __nv_bfloat162 p0 = __floats2bfloat162_rn(v.x, v.y);
        __nv_bfloat162 p1 = __floats2bfloat162_rn(v.z, v.w);
        uint2 o;
        o.x = *reinterpret_cast<uint32_t*>(&p0);
        o.y = *reinterpret_cast<uint32_t*>(&p1);
        *reinterpret_cast<uint2*>(g_Abf + (size_t)r * Dd + k) = o;

        if (r >= RT) {  // pad rows: just seed q with 0 (atomics may touch it)
            if (tid == 0) g_q[r] = 0.f;
            return;
        }

        float4 b4 = *reinterpret_cast<const float4*>(beta + k);
        float sin_ = v.x * v.x + v.y * v.y + v.z * v.z + v.w * v.w;
        float sb = b4.x * v.x + b4.y * v.y + b4.z * v.z + b4.w * v.w;
#pragma unroll
        for (int off = 16; off > 0; off >>= 1) {
            sin_ += __shfl_xor_sync(0xFFFFFFFFu, sin_, off);
            sb += __shfl_xor_sync(0xFFFFFFFFu, sb, off);
        }
        __shared__ float red[2][8];
        int wid = tid >> 5, lane = tid & 31;
        if (lane == 0) { red[0][wid] = sin_; red[1][wid] = sb; }
        __syncthreads();
        if (tid == 0) {
            float t0 = 0.f, t1 = 0.f;
#pragma unroll
            for (int wq = 0; wq < 8; wq++) { t0 += red[0][wq]; t1 += red[1][wq]; }
            g_q[r] = 1e-6f * t0;   // seed; gemm epilogue atomically adds ||MA||^2
            g_bd[r] = t1;
        }
    } else if (bid < PREP_Z0) {
        // ---- prepL: tril + transpose one 32x32 tile ----
        int tileId = bid - PREP_L0;
        int bx = (tileId & 31) * 32;   // k base
        int by = (tileId >> 5) * 32;   // n base
        __shared__ float t[32][33];
        int tx = tid & 31, ty = tid >> 5;  // 32 x 8
#pragma unroll
        for (int i = ty; i < 32; i += 8)
            t[i][tx] = L[(size_t)(bx + i) * Dd + by + tx];
        __syncthreads();
#pragma unroll
        for (int i = ty; i < 32; i += 8) {
            int n = by + i, k = bx + tx;
            float v = (k >= n) ? t[tx][i] : 0.f;
            g_Bbf[(size_t)n * Dd + k] = __float2bfloat16(v);
        }
    } else {
        // ---- zero g_dots ----
        int zb = bid - PREP_Z0;                 // 0..127
        int idx = (zb * 256 + tid) * 4;         // Bb*Dd = 131072 floats
        *reinterpret_cast<float4*>(g_dots + idx) =
            make_float4(0.f, 0.f, 0.f, 0.f);
    }
}

// ---------------------------------------------------------------------------
// 1) gemm_ma_mma: g_MAbf[m][n] = sum_k g_Abf[m][k] * g_Bbf[n][k]  (NT, bf16 HMMA)
//    BM=BN=64, BK=32, 128 thr, 2x2 warps, warp tile 32x32. Triangular K-skip.
//    Epilogue: row-norm partials (of ROUNDED bf16 values) atomically added
//    into g_q -> kills the separate manorm kernel.
// ---------------------------------------------------------------------------
__global__ __launch_bounds__(128) void gemm_ma_mma() {
    __shared__ __align__(16) __nv_bfloat16 As[64][40];
    __shared__ __align__(16) __nv_bfloat16 Bs[64][40];
    int bm = blockIdx.x * 64;
    int bn = blockIdx.y * 64;
    int tid = threadIdx.x;
    int lane = tid & 31, w = tid >> 5;
    int wm = (w & 1) * 32, wn = (w >> 1) * 32;

    int lr = tid >> 1;             // 0..63 (tile row)
    int lk = (tid & 1) * 16;       // 0 / 16 (bf16 units)
    const __nv_bfloat16* aptr = g_Abf + (size_t)(bm + lr) * Dd + lk;
    const __nv_bfloat16* bptr = g_Bbf + (size_t)(bn + lr) * Dd + lk;

    float acc[2][4][4];
#pragma unroll
    for (int mt = 0; mt < 2; mt++)
#pragma unroll
        for (int nt = 0; nt < 4; nt++)
#pragma unroll
            for (int e = 0; e < 4; e++) acc[mt][nt][e] = 0.f;

    uint32_t aAddr[2], bAddr[2];
#pragma unroll
    for (int t = 0; t < 2; t++) {
        aAddr[t] = (uint32_t)__cvta_generic_to_shared(
            &As[wm + t * 16 + (lane & 15)][(lane >> 4) * 8]);
        bAddr[t] = (uint32_t)__cvta_generic_to_shared(
            &Bs[wn + t * 16 + (lane & 15)][(lane >> 4) * 8]);
    }

    int kstart = bn;  // tril skip: L^T[n][k] = 0 for k < n
    uint4 pa0 = *reinterpret_cast<const uint4*>(aptr + kstart);
    uint4 pa1 = *reinterpret_cast<const uint4*>(aptr + kstart + 8);
    uint4 pb0 = *reinterpret_cast<const uint4*>(bptr + kstart);
    uint4 pb1 = *reinterpret_cast<const uint4*>(bptr + kstart + 8);

    for (int k0 = kstart; k0 < Dd; k0 += 32) {
        *reinterpret_cast<uint4*>(&As[lr][lk]) = pa0;
        *reinterpret_cast<uint4*>(&As[lr][lk + 8]) = pa1;
        *reinterpret_cast<uint4*>(&Bs[lr][lk]) = pb0;
        *reinterpret_cast<uint4*>(&Bs[lr][lk + 8]) = pb1;
        __syncthreads();
        if (k0 + 32 < Dd) {
            pa0 = *reinterpret_cast<const uint4*>(aptr + k0 + 32);
            pa1 = *reinterpret_cast<const uint4*>(aptr + k0 + 40);
            pb0 = *reinterpret_cast<const uint4*>(bptr + k0 + 32);
            pb1 = *reinterpret_cast<const uint4*>(bptr + k0 + 40);
        }
#pragma unroll
        for (int ks = 0; ks < 2; ks++) {
            uint32_t off = (uint32_t)(ks * 32);  // bytes (16 bf16)
            uint32_t a0[4], a1[4], br0[4], br1[4];
            ldsm_x4(a0[0], a0[1], a0[2], a0[3], aAddr[0] + off);
            ldsm_x4(a1[0], a1[1], a1[2], a1[3], aAddr[1] + off);
            ldsm_x4(br0[0], br0[1], br0[2], br0[3], bAddr[0] + off);
            ldsm_x4(br1[0], br1[1], br1[2], br1[3], bAddr[1] + off);
#pragma unroll
            for (int mt = 0; mt < 2; mt++) {
                uint32_t* a = mt ? a1 : a0;
                mma_bf16(acc[mt][0], a, br0[0], br0[2]);
                mma_bf16(acc[mt][1], a, br0[1], br0[3]);
                mma_bf16(acc[mt][2], a, br1[0], br1[2]);
                mma_bf16(acc[mt][3], a, br1[1], br1[3]);
            }
        }
        __syncthreads();
    }

    int mrow = lane >> 2;
    int ncol = (lane & 3) * 2;
#pragma unroll
    for (int mt = 0; mt < 2; mt++) {
        float s0 = 0.f, s1 = 0.f;  // norm partials of rounded values (rows mrow / mrow+8)
#pragma unroll
        for (int nt = 0; nt < 4; nt++) {
            int row = bm + wm + mt * 16 + mrow;
            int col = bn + wn + nt * 8 + ncol;
            __nv_bfloat162 lo = __floats2bfloat162_rn(acc[mt][nt][0], acc[mt][nt][1]);
            __nv_bfloat162 hi = __floats2bfloat162_rn(acc[mt][nt][2], acc[mt][nt][3]);
            *reinterpret_cast<__nv_bfloat162*>(g_MAbf + (size_t)row * Dd + col) = lo;
            *reinterpret_cast<__nv_bfloat162*>(g_MAbf + (size_t)(row + 8) * Dd + col) = hi;
            float l0 = __bfloat162float(lo.x), l1 = __bfloat162float(lo.y);
            float h0 = __bfloat162float(hi.x), h1 = __bfloat162float(hi.y);
            s0 += l0 * l0 + l1 * l1;
            s1 += h0 * h0 + h1 * h1;
        }
        // reduce across the 4 lanes sharing this row (lane & 3 differ)
        s0 += __shfl_xor_sync(0xFFFFFFFFu, s0, 1);
        s0 += __shfl_xor_sync(0xFFFFFFFFu, s0, 2);
        s1 += __shfl_xor_sync(0xFFFFFFFFu, s1, 1);
        s1 += __shfl_xor_sync(0xFFFFFFFFu, s1, 2);
        if ((lane & 3) == 0) {
            int row = bm + wm + mt * 16 + mrow;
            atomicAdd(&g_q[row], s0);
            atomicAdd(&g_q[row + 8], s1);
        }
    }
}

// ---------------------------------------------------------------------------
// 2) dot_mma: g_dots[b][c] += sum_{k in chunk z} MAbf[Cc+b][k] * MAbf[c][k]
//    Split-K=8 accumulated via atomics (g_dots zeroed in prep).
// ---------------------------------------------------------------------------
__global__ __launch_bounds__(128) void dot_mma() {
    __shared__ __align__(16) __nv_bfloat16 As[64][40];
    __shared__ __align__(16) __nv_bfloat16 Bs[64][40];
    int bm = blockIdx.x * 64;                // b offset
    int bn = blockIdx.y * 64;                // c offset
    int kb = blockIdx.z * KC;                // k chunk base
    int tid = threadIdx.x;
    int lane = tid & 31, w = tid >> 5;
    int wm = (w & 1) * 32, wn = (w >> 1) * 32;

    int lr = tid >> 1;
    int lk = (tid & 1) * 16;
    const __nv_bfloat16* aptr = g_MAbf + (size_t)(Cc + bm + lr) * Dd + kb + lk;
    const __nv_bfloat16* bptr = g_MAbf + (size_t)(bn + lr) * Dd + kb + lk;

    float acc[2][4][4];
#pragma unroll
    for (int mt = 0; mt < 2; mt++)
#pragma unroll
        for (int nt = 0; nt < 4; nt++)
#pragma unroll
            for (int e = 0; e < 4; e++) acc[mt][nt][e] = 0.f;

    uint32_t aAddr[2], bAddr[2];
#pragma unroll
    for (int t = 0; t < 2; t++) {
        aAddr[t] = (uint32_t)__cvta_generic_to_shared(
            &As[wm + t * 16 + (lane & 15)][(lane >> 4) * 8]);
        bAddr[t] = (uint32_t)__cvta_generic_to_shared(
            &Bs[wn + t * 16 + (lane & 15)][(lane >> 4) * 8]);
    }

    uint4 qa0 = *reinterpret_cast<const uint4*>(aptr);
    uint4 qa1 = *reinterpret_cast<const uint4*>(aptr + 8);
    uint4 qb0 = *reinterpret_cast<const uint4*>(bptr);
    uint4 qb1 = *reinterpret_cast<const uint4*>(bptr + 8);

#pragma unroll 1
    for (int k0 = 0; k0 < KC; k0 += 32) {
        *reinterpret_cast<uint4*>(&As[lr][lk]) = qa0;
        *reinterpret_cast<uint4*>(&As[lr][lk + 8]) = qa1;
        *reinterpret_cast<uint4*>(&Bs[lr][lk]) = qb0;
        *reinterpret_cast<uint4*>(&Bs[lr][lk + 8]) = qb1;
        __syncthreads();
        if (k0 + 32 < KC) {
            qa0 = *reinterpret_cast<const uint4*>(aptr + k0 + 32);
            qa1 = *reinterpret_cast<const uint4*>(aptr + k0 + 40);
            qb0 = *reinterpret_cast<const uint4*>(bptr + k0 + 32);
            qb1 = *reinterpret_cast<const uint4*>(bptr + k0 + 40);
        }
#pragma unroll
        for (int ks = 0; ks < 2; ks++) {
            uint32_t off = (uint32_t)(ks * 32);
            uint32_t a0[4], a1[4], br0[4], br1[4];
            ldsm_x4(a0[0], a0[1], a0[2], a0[3], aAddr[0] + off);
            ldsm_x4(a1[0], a1[1], a1[2], a1[3], aAddr[1] + off);
            ldsm_x4(br0[0], br0[1], br0[2], br0[3], bAddr[0] + off);
            ldsm_x4(br1[0], br1[1], br1[2], br1[3], bAddr[1] + off);
#pragma unroll
            for (int mt = 0; mt < 2; mt++) {
                uint32_t* a = mt ? a1 : a0;
                mma_bf16(acc[mt][0], a, br0[0], br0[2]);
                mma_bf16(acc[mt][1], a, br0[1], br0[3]);
                mma_bf16(acc[mt][2], a, br1[0], br1[2]);
                mma_bf16(acc[mt][3], a, br1[1], br1[3]);
            }
        }
        __syncthreads();
    }

    int mrow = lane >> 2;
    int ncol = (lane & 3) * 2;
#pragma unroll
    for (int mt = 0; mt < 2; mt++)
#pragma unroll
        for (int nt = 0; nt < 4; nt++) {
            int row = bm + wm + mt * 16 + mrow;
            int col = bn + wn + nt * 8 + ncol;
            float* p0 = g_dots + (size_t)row * Dd + col;
            float* p1 = g_dots + (size_t)(row + 8) * Dd + col;
            atomicAdd(p0, acc[mt][nt][0]);
            atomicAdd(p0 + 1, acc[mt][nt][1]);
            atomicAdd(p1, acc[mt][nt][2]);
            atomicAdd(p1 + 1, acc[mt][nt][3]);
        }
}

// ---------------------------------------------------------------------------
// 3) Finalize (reads 1 float of dots per output)
// ---------------------------------------------------------------------------
#define C4 (Cc / 4)   // 250
__global__ __launch_bounds__(128) void finalize(const float* __restrict__ lmbda,
                                                const float* __restrict__ scale,
                                                float* __restrict__ out) {
    int idx = blockIdx.x * 128 + threadIdx.x;
    if (idx >= Bb * C4) return;
    int b = idx / C4;
    int c = (idx - b * C4) * 4;

    float4 s = *reinterpret_cast<const float4*>(g_dots + (size_t)b * Dd + c);
    float qb = g_q[Cc + b];
    float bdb = g_bd[Cc + b];
    float lm = *lmbda;
    float sc = *scale;
    float4 o;
    {
        float quad = qb + g_q[c + 0] - 2.f * s.x;
        float bd = bdb - g_bd[c + 0];
        o.x = -sc * (sqrtf(quad + 1e-6f) + lm * sqrtf(bd * bd + 1e-6f));
    }
    {
        float quad = qb + g_q[c + 1] - 2.f * s.y;
        float bd = bdb - g_bd[c + 1];
        o.y = -sc * (sqrtf(quad + 1e-6f) + lm * sqrtf(bd * bd + 1e-6f));
    }
    {
        float quad = qb + g_q[c + 2] - 2.f * s.z;
        float bd = bdb - g_bd[c + 2];
        o.z = -sc * (sqrtf(quad + 1e-6f) + lm * sqrtf(bd * bd + 1e-6f));
    }
    {
        float quad = qb + g_q[c + 3] - 2.f * s.w;
        float bd = bdb - g_bd[c + 3];
        o.w = -sc * (sqrtf(quad + 1e-6f) + lm * sqrtf(bd * bd + 1e-6f));
    }
    *reinterpret_cast<float4*>(out + (size_t)b * Cc + c) = o;
}

// ---------------------------------------------------------------------------
extern "C" void kernel_launch(void* const* d_in, const int* in_sizes, int n_in,
                              void* d_out, int out_size) {
    const float *x = nullptr, *mu = nullptr, *beta = nullptr, *L = nullptr;
    const float *lmbda = nullptr, *scale = nullptr;
    for (int i = 0; i < n_in; i++) {
        const float* p = (const float*)d_in[i];
        switch (in_sizes[i]) {
            case Bb * Dd:  x = p; break;
            case Cc * Dd:  mu = p; break;
            case Dd:       beta = p; break;
            case Dd * Dd:  L = p; break;
            case 1:        if (!lmbda) lmbda = p; else scale = p; break;
            default: break;
        }
    }

    prep<<<MP + 1024 + 128, 256>>>(x, mu, beta, L);
    gemm_ma_mma<<<dim3(MP / 64, Dd / 64), 128>>>();
    dot_mma<<<dim3(Bb / 64, Dd / 64, KS), 128>>>();
    finalize<<<(Bb * C4 + 127) / 128, 128>>>(lmbda, scale, (float*)d_out);
}